// round 12
// baseline (speedup 1.0000x reference)
#include <cuda_runtime.h>
#include <math.h>

#define BB 8
#define QQ 4
#define HH 4096
#define NHEAD 32
#define NKV 8
#define HD 128
#define GG 4
#define NTOK (BB*QQ)                     // 32
#define QKV_COLS (NHEAD*HD + 2*NKV*HD)   // 6144
#define NSPLIT 27
#define ATT_SCALE 0.08838834764831845f   // 1/sqrt(128)

// ---- attention smem layout (floats), 2-stage pipeline (R9 config) ----
#define CH 8
#define ROW_K 516
#define ROW_V 520
#define OFF_VS (CH*ROW_K)                 // 4128
#define STG_FLOATS (CH*ROW_K + CH*ROW_V)  // 8288
#define OFF_MB_A (2*STG_FLOATS)           // 16576
#define SMEM_ATTN_BYTES (OFF_MB_A*4 + 32) // 66336

// ---- tensor-core GEMM config ----
#define GSPLIT 8
#define GKRANGE (HH/GSPLIT)               // 512
#define GK 32                             // 45KB smem -> 5 blocks/SM
#define GNCH (GKRANGE/GK)                 // 16
#define GPAD_A 40
#define GPAD_B 136
#define GOFF_B (2*GK*GPAD_A)              // 2560 floats
#define GSMEM_FLOATS (GOFF_B + 2*GK*GPAD_B)   // 11264
#define GSMEM_BYTES (GSMEM_FLOATS*4)          // 45056

// ---------------- device scratch ----------------
__device__ float g_part_qkv[GSPLIT*NTOK*QKV_COLS];
__device__ float g_q[NTOK*NHEAD*HD];
__device__ float g_k[NTOK*NKV*HD];
__device__ float g_v[NTOK*NKV*HD];
__device__ float g_po[BB*NKV*NSPLIT*16*HD];
__device__ float g_pml[BB*NKV*NSPLIT*16*2];
__device__ float g_attnT[HH*NTOK];
__device__ float g_part_out[GSPLIT*NTOK*HH];

// ---------------- tf32 / mma helpers ----------------
__device__ __forceinline__ float tf32r(float x) {
    unsigned u;
    asm("cvt.rna.tf32.f32 %0, %1;" : "=r"(u) : "f"(x));
    return __uint_as_float(u);
}
__device__ __forceinline__ void mma_tf32(float& d0, float& d1, float& d2, float& d3,
                                         float a0, float a1, float a2, float a3,
                                         float b0, float b1) {
    asm volatile(
        "mma.sync.aligned.m16n8k8.row.col.f32.tf32.tf32.f32 "
        "{%0,%1,%2,%3}, {%4,%5,%6,%7}, {%8,%9}, {%0,%1,%2,%3};"
        : "+f"(d0), "+f"(d1), "+f"(d2), "+f"(d3)
        : "r"(__float_as_uint(a0)), "r"(__float_as_uint(a1)),
          "r"(__float_as_uint(a2)), "r"(__float_as_uint(a3)),
          "r"(__float_as_uint(b0)), "r"(__float_as_uint(b1)));
}

// ---------------- mbarrier / bulk / cp.async helpers ----------------
__device__ __forceinline__ unsigned smem_u32(const void* p) {
    return (unsigned)__cvta_generic_to_shared(p);
}
__device__ __forceinline__ void mbar_init(unsigned mbar, unsigned count) {
    asm volatile("mbarrier.init.shared.b64 [%0], %1;" :: "r"(mbar), "r"(count) : "memory");
}
__device__ __forceinline__ void mbar_expect_tx(unsigned mbar, unsigned tx) {
    asm volatile("mbarrier.arrive.expect_tx.shared.b64 _, [%0], %1;"
                 :: "r"(mbar), "r"(tx) : "memory");
}
__device__ __forceinline__ void mbar_wait(unsigned mbar, int parity) {
    asm volatile(
        "{\n\t.reg .pred P;\n\t"
        "W_%=:\n\t"
        "mbarrier.try_wait.parity.acquire.cta.shared::cta.b64 P, [%0], %1, 0x989680;\n\t"
        "@P bra.uni D_%=;\n\t"
        "bra.uni W_%=;\n\t"
        "D_%=:\n\t}"
        :: "r"(mbar), "r"(parity) : "memory");
}
__device__ __forceinline__ void bulk_cp(unsigned dst, const void* src, unsigned bytes,
                                        unsigned mbar) {
    asm volatile(
        "cp.async.bulk.shared::cta.global.mbarrier::complete_tx::bytes [%0], [%1], %2, [%3];"
        :: "r"(dst), "l"(src), "r"(bytes), "r"(mbar) : "memory");
}
__device__ __forceinline__ void cp16(float* dstp, const float* src) {
    unsigned d = (unsigned)__cvta_generic_to_shared(dstp);
    asm volatile("cp.async.cg.shared.global [%0], [%1], 16;" :: "r"(d), "l"(src));
}
#define CP_COMMIT() asm volatile("cp.async.commit_group;")

// ---------------- shared tensor-core GEMM body ----------------
// TRANS_A=true: Asrc is hidden [32 tokens][4096] -> transpose+tf32r into A tile,
//   LDG prefetched one chunk ahead (overlaps previous chunk's MMAs).
// TRANS_A=false: Asrc is [K][32] pre-rounded (g_attnT), staged via cp.async.
template <bool TRANS_A>
__device__ __forceinline__ void gemm_body(const float* __restrict__ Asrc,
                                          const float* __restrict__ Wsrc,
                                          int wstride, int cb, int k0base,
                                          float* __restrict__ outb, int ostride,
                                          int colbase, float* gsm) {
    float* hA = gsm;
    float* wB = gsm + GOFF_B;
    int tid  = threadIdx.x;
    int warp = tid >> 5;
    int lane = tid & 31;
    int g    = lane >> 2;
    int t    = lane & 3;

    // A-transpose lane mapping
    int tok   = tid & 31;
    int rbase = (tid >> 5) * 8;

    float c[2][4][4];
    #pragma unroll
    for (int m = 0; m < 2; m++)
        #pragma unroll
        for (int j = 0; j < 4; j++)
            #pragma unroll
            for (int v = 0; v < 4; v++) c[m][j][v] = 0.f;

    auto stageW = [&](int buf, int kc) {
        int k0 = k0base + kc*GK;
        #pragma unroll
        for (int i = 0; i < 8; i++) {
            int idx = tid + i*128;
            int r = idx >> 5, c4 = idx & 31;
            cp16(wB + buf*GK*GPAD_B + r*GPAD_B + c4*4,
                 Wsrc + (size_t)(k0 + r)*wstride + cb + c4*4);
        }
    };
    auto stageA_cp = [&](int buf, int kc) {
        int k0 = k0base + kc*GK;
        #pragma unroll
        for (int i = 0; i < 2; i++) {
            int idx = tid + i*128;
            int r = idx >> 3, c4 = idx & 7;
            cp16(hA + buf*GK*GPAD_A + r*GPAD_A + c4*4,
                 Asrc + (size_t)(k0 + r)*NTOK + c4*4);
        }
    };
    auto ldgA = [&](int kc, float4& x, float4& y) {
        const float4* p = (const float4*)(Asrc + (size_t)tok*HH + k0base + kc*GK + rbase);
        x = p[0]; y = p[1];
    };
    auto stsA = [&](int buf, float4 x, float4 y) {
        float* d = hA + buf*GK*GPAD_A + rbase*GPAD_A + tok;
        d[0*GPAD_A] = tf32r(x.x); d[1*GPAD_A] = tf32r(x.y);
        d[2*GPAD_A] = tf32r(x.z); d[3*GPAD_A] = tf32r(x.w);
        d[4*GPAD_A] = tf32r(y.x); d[5*GPAD_A] = tf32r(y.y);
        d[6*GPAD_A] = tf32r(y.z); d[7*GPAD_A] = tf32r(y.w);
    };

    float4 ax, ay;
    if (TRANS_A) {
        ldgA(0, ax, ay);
        stsA(0, ax, ay);
        stageW(0, 0);
    } else {
        stageA_cp(0, 0);
        stageW(0, 0);
    }
    CP_COMMIT();

    for (int kc = 0; kc < GNCH; kc++) {
        int buf = kc & 1;
        if (kc + 1 < GNCH) {
            if (TRANS_A) {
                ldgA(kc + 1, ax, ay);       // in flight during compute below
                stageW(buf ^ 1, kc + 1);
            } else {
                stageA_cp(buf ^ 1, kc + 1);
                stageW(buf ^ 1, kc + 1);
            }
            CP_COMMIT();
            asm volatile("cp.async.wait_group 1;");
        } else {
            asm volatile("cp.async.wait_group 0;");
        }
        __syncthreads();

        const float* hb = hA + buf*GK*GPAD_A;
        const float* wb = wB + buf*GK*GPAD_B;
        #pragma unroll
        for (int ks = 0; ks < GK/8; ks++) {
            int kb = ks * 8;
            float a[2][4];
            #pragma unroll
            for (int m = 0; m < 2; m++) {
                int m0 = m*16;
                a[m][0] = hb[(kb+t)*GPAD_A   + m0 + g];
                a[m][1] = hb[(kb+t)*GPAD_A   + m0 + g + 8];
                a[m][2] = hb[(kb+t+4)*GPAD_A + m0 + g];
                a[m][3] = hb[(kb+t+4)*GPAD_A + m0 + g + 8];
            }
            #pragma unroll
            for (int j = 0; j < 4; j++) {
                int n = warp*32 + j*8 + g;
                float b0 = tf32r(wb[(kb+t)*GPAD_B   + n]);
                float b1 = tf32r(wb[(kb+t+4)*GPAD_B + n]);
                mma_tf32(c[0][j][0], c[0][j][1], c[0][j][2], c[0][j][3],
                         a[0][0], a[0][1], a[0][2], a[0][3], b0, b1);
                mma_tf32(c[1][j][0], c[1][j][1], c[1][j][2], c[1][j][3],
                         a[1][0], a[1][1], a[1][2], a[1][3], b0, b1);
            }
        }
        if (TRANS_A && kc + 1 < GNCH)
            stsA(buf ^ 1, ax, ay);          // others still read buf, not buf^1
        __syncthreads();
    }

    #pragma unroll
    for (int m = 0; m < 2; m++)
        #pragma unroll
        for (int j = 0; j < 4; j++) {
            int col = colbase + warp*32 + j*8 + 2*t;
            int r0  = m*16 + g;
            *(float2*)&outb[(size_t)r0*ostride + col] =
                make_float2(c[m][j][0], c[m][j][1]);
            *(float2*)&outb[(size_t)(r0+8)*ostride + col] =
                make_float2(c[m][j][2], c[m][j][3]);
        }
}

// ---------------- 1. QKV GEMM (tf32 mma, K-split, fused hidden transpose) ----------------
__global__ void __launch_bounds__(128) k_gemm_qkv(const float* __restrict__ hidden,
                                                  const float* __restrict__ Wq,
                                                  const float* __restrict__ Wk,
                                                  const float* __restrict__ Wv) {
    extern __shared__ float gsm[];
    int colbase = blockIdx.x * 128;
    const float* Wsrc; int wstride, cb;
    if (colbase < 4096)       { Wsrc = Wq; wstride = 4096; cb = colbase; }
    else if (colbase < 5120)  { Wsrc = Wk; wstride = 1024; cb = colbase - 4096; }
    else                      { Wsrc = Wv; wstride = 1024; cb = colbase - 5120; }
    float* outb = g_part_qkv + (size_t)blockIdx.y * NTOK * QKV_COLS;
    gemm_body<true>(hidden, Wsrc, wstride, cb, blockIdx.y * GKRANGE,
                    outb, QKV_COLS, colbase, gsm);
}

// ---------------- 2. reduce K-splits + RoPE ----------------
__global__ void k_reduce_rope(const float* __restrict__ cosb,
                              const float* __restrict__ sinb) {
    int slot = blockIdx.x;
    int row  = blockIdx.y;
    int d    = threadIdx.x;
    int col  = slot*128 + d;

    float s = 0.f;
    #pragma unroll
    for (int i = 0; i < GSPLIT; i++)
        s += g_part_qkv[((size_t)i*NTOK + row)*QKV_COLS + col];

    __shared__ float x[128];
    x[d] = s;
    __syncthreads();

    if (slot < 40) {
        float c  = cosb[row*128 + d];
        float sn = sinb[row*128 + d];
        float rot = (d < 64) ? -x[d + 64] : x[d - 64];
        float val = s*c + rot*sn;
        if (slot < 32) g_q[(size_t)row*4096 + col] = val;
        else           g_k[(size_t)row*1024 + (slot-32)*128 + d] = val;
    } else {
        g_v[(size_t)row*1024 + (slot-40)*128 + d] = s;
    }
}

// ---------------- 3. attention: R9 config (2-stage, 4 heads/block, 2KB TMA) ----------------
__device__ __forceinline__ void stage8(float* sm, unsigned mbK, unsigned mbV,
        int stg, int c0, int cl, int s1, int b, int kv0, int cap,
        const float* Kc, const float* Vc, int tid) {
    int nv = min(CH, s1 - c0);
    if (tid == 0) {
        mbar_expect_tx(mbK, (unsigned)nv * 2048u);
        mbar_expect_tx(mbV, (unsigned)nv * 2048u);
    }
    if (tid < 16) {
        int p = tid & 7;
        if (p < nv) {
            int sg = c0 + p;
            bool isV = tid >= 8;
            const float* src;
            if (sg < cl) {
                src = (isV ? Vc : Kc) + (((size_t)b*cap + sg)*NKV + kv0)*HD;
            } else {
                int row = b*QQ + (sg - cl);
                src = (isV ? g_v : g_k) + ((size_t)row*(NKV*HD) + kv0*HD);
            }
            float* dstp = sm + stg*STG_FLOATS + (isV ? OFF_VS + p*ROW_V : p*ROW_K);
            bulk_cp(smem_u32(dstp), src, 2048u, isV ? mbV : mbK);
        }
    }
}

__global__ void __launch_bounds__(128, 3) k_attn(const float* __restrict__ Kc,
                       const float* __restrict__ Vc,
                       const int* __restrict__ cache_lens, int cap) {
    extern __shared__ float sm[];
    unsigned mbb  = smem_u32(sm + OFF_MB_A);
    unsigned mbK0 = mbb,       mbK1 = mbb + 8;
    unsigned mbV0 = mbb + 16,  mbV1 = mbb + 24;

    int tid  = threadIdx.x;
    int warp = tid >> 5;
    int lane = tid & 31;
    int g    = lane >> 2;
    int t    = lane & 3;

    int split = blockIdx.x;
    int kv0   = blockIdx.y * 4;
    int b     = blockIdx.z;
    int kvh   = kv0 + warp;

    int cl = cache_lens[b];
    int n_total = cl + QQ;
    int len = (n_total + NSPLIT - 1) / NSPLIT;
    int s0 = split * len;
    int s1 = min(s0 + len, n_total);
    size_t pbase = (((size_t)(b*NKV + kvh))*NSPLIT + split)*16;

    if (s0 >= s1) {
        if (lane < 16) {
            g_pml[(pbase + lane)*2]     = -1e30f;
            g_pml[(pbase + lane)*2 + 1] = 0.f;
        }
        for (int i = lane; i < 16*HD; i += 32)
            g_po[pbase*HD + i] = 0.f;
        return;
    }

    if (tid == 0) {
        mbar_init(mbK0, 1); mbar_init(mbK1, 1);
        mbar_init(mbV0, 1); mbar_init(mbV1, 1);
    }

    float aq[16][4];
    {
        int row0  = b*QQ + (g >> 2);
        int hq0   = kvh*GG + (g & 3);
        int row1  = b*QQ + ((g + 8) >> 2);
        int hq1   = kvh*GG + ((g + 8) & 3);
        const float* q0 = g_q + (size_t)row0*4096 + hq0*128;
        const float* q1 = g_q + (size_t)row1*4096 + hq1*128;
        #pragma unroll
        for (int ks = 0; ks < 16; ks++) {
            int kb = ks * 8;
            aq[ks][0] = tf32r(q0[kb + t]     * ATT_SCALE);
            aq[ks][1] = tf32r(q1[kb + t]     * ATT_SCALE);
            aq[ks][2] = tf32r(q0[kb + t + 4] * ATT_SCALE);
            aq[ks][3] = tf32r(q1[kb + t + 4] * ATT_SCALE);
        }
    }
    __syncthreads();

    float l0 = 0.f, l1 = 0.f;
    float oacc[16][4];
    #pragma unroll
    for (int nt = 0; nt < 16; nt++)
        #pragma unroll
        for (int j = 0; j < 4; j++) oacc[nt][j] = 0.f;

    int nch = (s1 - s0 + CH - 1) / CH;
    stage8(sm, mbK0, mbV0, 0, s0, cl, s1, b, kv0, cap, Kc, Vc, tid);

    for (int ci = 0; ci < nch; ci++) {
        int c0 = s0 + ci*CH;
        int bf = ci & 1;
        int par = (ci >> 1) & 1;

        if (ci + 1 < nch) {
            __syncthreads();
            stage8(sm, bf ? mbK0 : mbK1, bf ? mbV0 : mbV1, bf ^ 1,
                   c0 + CH, cl, s1, b, kv0, cap, Kc, Vc, tid);
        }

        mbar_wait(bf ? mbK1 : mbK0, par);

        float cA0 = 0.f, cA1 = 0.f, cA2 = 0.f, cA3 = 0.f;
        float cB0 = 0.f, cB1 = 0.f, cB2 = 0.f, cB3 = 0.f;
        {
            const float* Kb = sm + bf*STG_FLOATS + g*ROW_K + warp*128;
            #pragma unroll
            for (int ks = 0; ks < 16; ks += 2) {
                int kb = ks * 8;
                float b0 = Kb[kb + t];
                float b1 = Kb[kb + t + 4];
                mma_tf32(cA0, cA1, cA2, cA3,
                         aq[ks][0], aq[ks][1], aq[ks][2], aq[ks][3], b0, b1);
                float b2 = Kb[kb + 8 + t];
                float b3 = Kb[kb + 8 + t + 4];
                mma_tf32(cB0, cB1, cB2, cB3,
                         aq[ks+1][0], aq[ks+1][1], aq[ks+1][2], aq[ks+1][3], b2, b3);
            }
        }
        float c0r = cA0 + cB0, c1r = cA1 + cB1;
        float c2r = cA2 + cB2, c3r = cA3 + cB3;

        int Lg = min(s1, cl + (g >> 2) + 1) - c0;
        int Lh = min(s1, cl + ((g + 8) >> 2) + 1) - c0;
        int pc0 = 2*t, pc1 = 2*t + 1;

        float e00 = (pc0 < Lg) ? __expf(c0r) : 0.f;
        float e01 = (pc1 < Lg) ? __expf(c1r) : 0.f;
        float e10 = (pc0 < Lh) ? __expf(c2r) : 0.f;
        float e11 = (pc1 < Lh) ? __expf(c3r) : 0.f;

        l0 += e00 + e01;
        l1 += e10 + e11;

        e00 = tf32r(e00); e01 = tf32r(e01); e10 = tf32r(e10); e11 = tf32r(e11);

        int srcA = (g << 2) | (t >> 1);
        int srcB = srcA + 2;
        float f0a = __shfl_sync(0xffffffffu, e00, srcA);
        float f1a = __shfl_sync(0xffffffffu, e01, srcA);
        float f0b = __shfl_sync(0xffffffffu, e00, srcB);
        float f1b = __shfl_sync(0xffffffffu, e01, srcB);
        float h0a = __shfl_sync(0xffffffffu, e10, srcA);
        float h1a = __shfl_sync(0xffffffffu, e11, srcA);
        float h0b = __shfl_sync(0xffffffffu, e10, srcB);
        float h1b = __shfl_sync(0xffffffffu, e11, srcB);
        bool odd = (t & 1);
        float a0 = odd ? f1a : f0a;
        float a1 = odd ? h1a : h0a;
        float a2 = odd ? f1b : f0b;
        float a3 = odd ? h1b : h0b;

        mbar_wait(bf ? mbV1 : mbV0, par);

        {
            const float* Vb = sm + bf*STG_FLOATS + OFF_VS + warp*128;
            const float* Vr0 = Vb + t*ROW_V;
            const float* Vr1 = Vb + (t + 4)*ROW_V;
            #pragma unroll
            for (int nt = 0; nt < 16; nt++) {
                int n0 = nt*8 + g;
                float b0 = Vr0[n0];
                float b1 = Vr1[n0];
                mma_tf32(oacc[nt][0], oacc[nt][1], oacc[nt][2], oacc[nt][3],
                         a0, a1, a2, a3, b0, b1);
            }
        }
    }

    l0 += __shfl_xor_sync(0xffffffffu, l0, 1);
    l0 += __shfl_xor_sync(0xffffffffu, l0, 2);
    l1 += __shfl_xor_sync(0xffffffffu, l1, 1);
    l1 += __shfl_xor_sync(0xffffffffu, l1, 2);

    #pragma unroll
    for (int nt = 0; nt < 16; nt++) {
        int col = nt*8 + 2*t;
        *(float2*)(g_po + (pbase + g    )*HD + col) = make_float2(oacc[nt][0], oacc[nt][1]);
        *(float2*)(g_po + (pbase + g + 8)*HD + col) = make_float2(oacc[nt][2], oacc[nt][3]);
    }
    if (t == 0) {
        g_pml[(pbase + g)*2]          = 0.f;
        g_pml[(pbase + g)*2 + 1]      = l0;
        g_pml[(pbase + g + 8)*2]      = 0.f;
        g_pml[(pbase + g + 8)*2 + 1]  = l1;
    }
}

// ---------------- 4. combine split partials -> attnT (tf32 round) ----------------
__global__ void k_combine() {
    int bkv = blockIdx.x;
    int b = bkv >> 3, kv = bkv & 7;
    int tid = threadIdx.x;
    int qi = tid >> 4, dg = tid & 15;
    int d0 = dg * 8;
    size_t base = (size_t)bkv * NSPLIT * 16;

    float m_tot = -1e30f;
    for (int s = 0; s < NSPLIT; s++)
        m_tot = fmaxf(m_tot, g_pml[(base + s*16 + qi)*2]);

    float o[8];
    #pragma unroll
    for (int j = 0; j < 8; j++) o[j] = 0.f;
    float l_tot = 0.f;

    for (int s = 0; s < NSPLIT; s++) {
        float m = g_pml[(base + s*16 + qi)*2];
        float l = g_pml[(base + s*16 + qi)*2 + 1];
        float w = (m <= -1e29f) ? 0.f : __expf(m - m_tot);
        l_tot += w * l;
        const float4* op = (const float4*)(g_po + (base + s*16 + qi)*HD + d0);
        float4 x0 = op[0], x1 = op[1];
        o[0] += w*x0.x; o[1] += w*x0.y; o[2] += w*x0.z; o[3] += w*x0.w;
        o[4] += w*x1.x; o[5] += w*x1.y; o[6] += w*x1.z; o[7] += w*x1.w;
    }
    float inv = 1.f / l_tot;
    int qo = qi >> 2, g = qi & 3;
    int row  = b*QQ + qo;
    int head = kv*GG + g;
    #pragma unroll
    for (int j = 0; j < 8; j++)
        g_attnT[(size_t)(head*128 + d0 + j)*NTOK + row] = tf32r(o[j] * inv);
}

// ---------------- 5. O GEMM (tf32 mma, K-split) ----------------
__global__ void __launch_bounds__(128) k_gemm_o(const float* __restrict__ Wo) {
    extern __shared__ float gsm[];
    int colbase = blockIdx.x * 128;
    float* outb = g_part_out + (size_t)blockIdx.y * NTOK * HH;
    gemm_body<false>(g_attnT, Wo, 4096, colbase, blockIdx.y * GKRANGE,
                     outb, HH, colbase, gsm);
}

// ---------------- 6. reduce O partials -> output ----------------
__global__ void k_reduce_out(float* __restrict__ out) {
    int idx = blockIdx.x * 256 + threadIdx.x;
    float s = 0.f;
    #pragma unroll
    for (int i = 0; i < GSPLIT; i++)
        s += g_part_out[(size_t)i * NTOK * HH + idx];
    out[idx] = s;
}

// ---------------- launch ----------------
extern "C" void kernel_launch(void* const* d_in, const int* in_sizes, int n_in,
                              void* d_out, int out_size) {
    const float* hidden = (const float*)d_in[0];
    const float* cosb   = (const float*)d_in[1];
    const float* sinb   = (const float*)d_in[2];
    const float* Wq     = (const float*)d_in[3];
    const float* Wk     = (const float*)d_in[4];
    const float* Wv     = (const float*)d_in[5];
    const float* Wo     = (const float*)d_in[6];
    const float* Kc     = (const float*)d_in[7];
    const float* Vc     = (const float*)d_in[8];
    const int*   cls    = (const int*)d_in[9];
    int cap = in_sizes[7] / (BB * NKV * HD);   // 4100

    static int attr_set = 0;
    if (!attr_set) {
        cudaFuncSetAttribute(k_attn, cudaFuncAttributeMaxDynamicSharedMemorySize,
                             SMEM_ATTN_BYTES);
        cudaFuncSetAttribute(k_gemm_qkv, cudaFuncAttributeMaxDynamicSharedMemorySize,
                             GSMEM_BYTES);
        cudaFuncSetAttribute(k_gemm_o, cudaFuncAttributeMaxDynamicSharedMemorySize,
                             GSMEM_BYTES);
        attr_set = 1;
    }

    k_gemm_qkv   <<<dim3(48, GSPLIT), 128, GSMEM_BYTES>>>(hidden, Wq, Wk, Wv);
    k_reduce_rope<<<dim3(48, NTOK), 128>>>(cosb, sinb);
    k_attn       <<<dim3(NSPLIT, 2, BB), 128, SMEM_ATTN_BYTES>>>(Kc, Vc, cls, cap);
    k_combine    <<<64, 256>>>();
    k_gemm_o     <<<dim3(32, GSPLIT), 128, GSMEM_BYTES>>>(Wo);
    k_reduce_out <<<512, 256>>>((float*)d_out);
}

// round 13
// speedup vs baseline: 1.0212x; 1.0212x over previous
#include <cuda_runtime.h>
#include <math.h>

#define BB 8
#define QQ 4
#define HH 4096
#define NHEAD 32
#define NKV 8
#define HD 128
#define GG 4
#define NTOK (BB*QQ)                     // 32
#define QKV_COLS (NHEAD*HD + 2*NKV*HD)   // 6144
#define NSPLIT 27
#define ATT_SCALE 0.08838834764831845f   // 1/sqrt(128)

// ---- attention smem layout (floats), 2-stage pipeline (R9 config) ----
#define CH 8
#define ROW_K 516
#define ROW_V 520
#define OFF_VS (CH*ROW_K)                 // 4128
#define STG_FLOATS (CH*ROW_K + CH*ROW_V)  // 8288
#define OFF_MB_A (2*STG_FLOATS)           // 16576
#define SMEM_ATTN_BYTES (OFF_MB_A*4 + 32) // 66336

// ---- tensor-core GEMM config ----
#define GSPLIT 8
#define GKRANGE (HH/GSPLIT)               // 512
#define GK 32                             // 45KB smem -> 5 blocks/SM
#define GNCH (GKRANGE/GK)                 // 16
#define GPAD_A 40
#define GPAD_B 136
#define GOFF_B (2*GK*GPAD_A)              // 2560 floats
#define GSMEM_FLOATS (GOFF_B + 2*GK*GPAD_B)   // 11264
#define GSMEM_BYTES (GSMEM_FLOATS*4)          // 45056

// ---------------- device scratch ----------------
__device__ float g_hT[HH*NTOK];
__device__ float g_part_qkv[GSPLIT*NTOK*QKV_COLS];
__device__ float g_q[NTOK*NHEAD*HD];
__device__ float g_k[NTOK*NKV*HD];
__device__ float g_v[NTOK*NKV*HD];
__device__ float g_po[BB*NKV*NSPLIT*16*HD];
__device__ float g_pml[BB*NKV*NSPLIT*16*2];
__device__ float g_attnT[HH*NTOK];
__device__ float g_part_out[GSPLIT*NTOK*HH];

// ---------------- tf32 / mma helpers ----------------
__device__ __forceinline__ float tf32r(float x) {
    unsigned u;
    asm("cvt.rna.tf32.f32 %0, %1;" : "=r"(u) : "f"(x));
    return __uint_as_float(u);
}
__device__ __forceinline__ void mma_tf32(float& d0, float& d1, float& d2, float& d3,
                                         float a0, float a1, float a2, float a3,
                                         float b0, float b1) {
    asm volatile(
        "mma.sync.aligned.m16n8k8.row.col.f32.tf32.tf32.f32 "
        "{%0,%1,%2,%3}, {%4,%5,%6,%7}, {%8,%9}, {%0,%1,%2,%3};"
        : "+f"(d0), "+f"(d1), "+f"(d2), "+f"(d3)
        : "r"(__float_as_uint(a0)), "r"(__float_as_uint(a1)),
          "r"(__float_as_uint(a2)), "r"(__float_as_uint(a3)),
          "r"(__float_as_uint(b0)), "r"(__float_as_uint(b1)));
}

// ---------------- mbarrier / bulk / cp.async helpers ----------------
__device__ __forceinline__ unsigned smem_u32(const void* p) {
    return (unsigned)__cvta_generic_to_shared(p);
}
__device__ __forceinline__ void mbar_init(unsigned mbar, unsigned count) {
    asm volatile("mbarrier.init.shared.b64 [%0], %1;" :: "r"(mbar), "r"(count) : "memory");
}
__device__ __forceinline__ void mbar_expect_tx(unsigned mbar, unsigned tx) {
    asm volatile("mbarrier.arrive.expect_tx.shared.b64 _, [%0], %1;"
                 :: "r"(mbar), "r"(tx) : "memory");
}
__device__ __forceinline__ void mbar_wait(unsigned mbar, int parity) {
    asm volatile(
        "{\n\t.reg .pred P;\n\t"
        "W_%=:\n\t"
        "mbarrier.try_wait.parity.acquire.cta.shared::cta.b64 P, [%0], %1, 0x989680;\n\t"
        "@P bra.uni D_%=;\n\t"
        "bra.uni W_%=;\n\t"
        "D_%=:\n\t}"
        :: "r"(mbar), "r"(parity) : "memory");
}
__device__ __forceinline__ void bulk_cp(unsigned dst, const void* src, unsigned bytes,
                                        unsigned mbar) {
    asm volatile(
        "cp.async.bulk.shared::cta.global.mbarrier::complete_tx::bytes [%0], [%1], %2, [%3];"
        :: "r"(dst), "l"(src), "r"(bytes), "r"(mbar) : "memory");
}
__device__ __forceinline__ void cp16(float* dstp, const float* src) {
    unsigned d = (unsigned)__cvta_generic_to_shared(dstp);
    asm volatile("cp.async.cg.shared.global [%0], [%1], 16;" :: "r"(d), "l"(src));
}
#define CP_COMMIT() asm volatile("cp.async.commit_group;")

// ---------------- 1. transpose hidden (pre-round to tf32) ----------------
__global__ void k_transpose(const float* __restrict__ x) {
    int idx = blockIdx.x * 256 + threadIdx.x;
    int r = idx >> 12;
    int k = idx & 4095;
    g_hT[k*NTOK + r] = tf32r(x[idx]);
}

// ---------------- shared tensor-core GEMM body (cp.async A staging) ----------------
__device__ __forceinline__ void gemm_body(const float* __restrict__ Asrc,
                                          const float* __restrict__ Wsrc,
                                          int wstride, int cb, int k0base,
                                          float* __restrict__ outb, int ostride,
                                          int colbase, float* gsm) {
    float* hA = gsm;
    float* wB = gsm + GOFF_B;
    int tid  = threadIdx.x;
    int warp = tid >> 5;
    int lane = tid & 31;
    int g    = lane >> 2;
    int t    = lane & 3;

    float c[2][4][4];
    #pragma unroll
    for (int m = 0; m < 2; m++)
        #pragma unroll
        for (int j = 0; j < 4; j++)
            #pragma unroll
            for (int v = 0; v < 4; v++) c[m][j][v] = 0.f;

    auto stage = [&](int buf, int kc) {
        int k0 = k0base + kc*GK;
        #pragma unroll
        for (int i = 0; i < 2; i++) {
            int idx = tid + i*128;
            int r = idx >> 3, c4 = idx & 7;
            cp16(hA + buf*GK*GPAD_A + r*GPAD_A + c4*4,
                 Asrc + (size_t)(k0 + r)*NTOK + c4*4);
        }
        #pragma unroll
        for (int i = 0; i < 8; i++) {
            int idx = tid + i*128;
            int r = idx >> 5, c4 = idx & 31;
            cp16(wB + buf*GK*GPAD_B + r*GPAD_B + c4*4,
                 Wsrc + (size_t)(k0 + r)*wstride + cb + c4*4);
        }
    };

    stage(0, 0);
    CP_COMMIT();

    for (int kc = 0; kc < GNCH; kc++) {
        int buf = kc & 1;
        if (kc + 1 < GNCH) {
            stage(buf ^ 1, kc + 1);
            CP_COMMIT();
            asm volatile("cp.async.wait_group 1;");
        } else {
            asm volatile("cp.async.wait_group 0;");
        }
        __syncthreads();

        const float* hb = hA + buf*GK*GPAD_A;
        const float* wb = wB + buf*GK*GPAD_B;
        #pragma unroll
        for (int ks = 0; ks < GK/8; ks++) {
            int kb = ks * 8;
            float a[2][4];
            #pragma unroll
            for (int m = 0; m < 2; m++) {
                int m0 = m*16;
                a[m][0] = hb[(kb+t)*GPAD_A   + m0 + g];
                a[m][1] = hb[(kb+t)*GPAD_A   + m0 + g + 8];
                a[m][2] = hb[(kb+t+4)*GPAD_A + m0 + g];
                a[m][3] = hb[(kb+t+4)*GPAD_A + m0 + g + 8];
            }
            #pragma unroll
            for (int j = 0; j < 4; j++) {
                int n = warp*32 + j*8 + g;
                float b0 = tf32r(wb[(kb+t)*GPAD_B   + n]);
                float b1 = tf32r(wb[(kb+t+4)*GPAD_B + n]);
                mma_tf32(c[0][j][0], c[0][j][1], c[0][j][2], c[0][j][3],
                         a[0][0], a[0][1], a[0][2], a[0][3], b0, b1);
                mma_tf32(c[1][j][0], c[1][j][1], c[1][j][2], c[1][j][3],
                         a[1][0], a[1][1], a[1][2], a[1][3], b0, b1);
            }
        }
        __syncthreads();
    }

    #pragma unroll
    for (int m = 0; m < 2; m++)
        #pragma unroll
        for (int j = 0; j < 4; j++) {
            int col = colbase + warp*32 + j*8 + 2*t;
            int r0  = m*16 + g;
            *(float2*)&outb[(size_t)r0*ostride + col] =
                make_float2(c[m][j][0], c[m][j][1]);
            *(float2*)&outb[(size_t)(r0+8)*ostride + col] =
                make_float2(c[m][j][2], c[m][j][3]);
        }
}

// ---------------- 2. QKV GEMM (tf32 mma, K-split) ----------------
__global__ void __launch_bounds__(128) k_gemm_qkv(const float* __restrict__ Wq,
                                                  const float* __restrict__ Wk,
                                                  const float* __restrict__ Wv) {
    extern __shared__ float gsm[];
    int colbase = blockIdx.x * 128;
    const float* Wsrc; int wstride, cb;
    if (colbase < 4096)       { Wsrc = Wq; wstride = 4096; cb = colbase; }
    else if (colbase < 5120)  { Wsrc = Wk; wstride = 1024; cb = colbase - 4096; }
    else                      { Wsrc = Wv; wstride = 1024; cb = colbase - 5120; }
    float* outb = g_part_qkv + (size_t)blockIdx.y * NTOK * QKV_COLS;
    gemm_body(g_hT, Wsrc, wstride, cb, blockIdx.y * GKRANGE,
              outb, QKV_COLS, colbase, gsm);
}

// ---------------- 3. reduce K-splits + RoPE ----------------
__global__ void k_reduce_rope(const float* __restrict__ cosb,
                              const float* __restrict__ sinb) {
    int slot = blockIdx.x;
    int row  = blockIdx.y;
    int d    = threadIdx.x;
    int col  = slot*128 + d;

    float s = 0.f;
    #pragma unroll
    for (int i = 0; i < GSPLIT; i++)
        s += g_part_qkv[((size_t)i*NTOK + row)*QKV_COLS + col];

    __shared__ float x[128];
    x[d] = s;
    __syncthreads();

    if (slot < 40) {
        float c  = cosb[row*128 + d];
        float sn = sinb[row*128 + d];
        float rot = (d < 64) ? -x[d + 64] : x[d - 64];
        float val = s*c + rot*sn;
        if (slot < 32) g_q[(size_t)row*4096 + col] = val;
        else           g_k[(size_t)row*1024 + (slot-32)*128 + d] = val;
    } else {
        g_v[(size_t)row*1024 + (slot-40)*128 + d] = s;
    }
}

// ---------------- 4. attention: R9 config (2-stage, 4 heads/block, 2KB TMA) ----------------
__device__ __forceinline__ void stage8(float* sm, unsigned mbK, unsigned mbV,
        int stg, int c0, int cl, int s1, int b, int kv0, int cap,
        const float* Kc, const float* Vc, int tid) {
    int nv = min(CH, s1 - c0);
    if (tid == 0) {
        mbar_expect_tx(mbK, (unsigned)nv * 2048u);
        mbar_expect_tx(mbV, (unsigned)nv * 2048u);
    }
    if (tid < 16) {
        int p = tid & 7;
        if (p < nv) {
            int sg = c0 + p;
            bool isV = tid >= 8;
            const float* src;
            if (sg < cl) {
                src = (isV ? Vc : Kc) + (((size_t)b*cap + sg)*NKV + kv0)*HD;
            } else {
                int row = b*QQ + (sg - cl);
                src = (isV ? g_v : g_k) + ((size_t)row*(NKV*HD) + kv0*HD);
            }
            float* dstp = sm + stg*STG_FLOATS + (isV ? OFF_VS + p*ROW_V : p*ROW_K);
            bulk_cp(smem_u32(dstp), src, 2048u, isV ? mbV : mbK);
        }
    }
}

__global__ void __launch_bounds__(128, 3) k_attn(const float* __restrict__ Kc,
                       const float* __restrict__ Vc,
                       const int* __restrict__ cache_lens, int cap) {
    extern __shared__ float sm[];
    unsigned mbb  = smem_u32(sm + OFF_MB_A);
    unsigned mbK0 = mbb,       mbK1 = mbb + 8;
    unsigned mbV0 = mbb + 16,  mbV1 = mbb + 24;

    int tid  = threadIdx.x;
    int warp = tid >> 5;
    int lane = tid & 31;
    int g    = lane >> 2;
    int t    = lane & 3;

    int split = blockIdx.x;
    int kv0   = blockIdx.y * 4;
    int b     = blockIdx.z;
    int kvh   = kv0 + warp;

    int cl = cache_lens[b];
    int n_total = cl + QQ;
    int len = (n_total + NSPLIT - 1) / NSPLIT;
    int s0 = split * len;
    int s1 = min(s0 + len, n_total);
    size_t pbase = (((size_t)(b*NKV + kvh))*NSPLIT + split)*16;

    if (s0 >= s1) {
        if (lane < 16) {
            g_pml[(pbase + lane)*2]     = 0.f;
            g_pml[(pbase + lane)*2 + 1] = 0.f;
        }
        for (int i = lane; i < 16*HD; i += 32)
            g_po[pbase*HD + i] = 0.f;
        return;
    }

    if (tid == 0) {
        mbar_init(mbK0, 1); mbar_init(mbK1, 1);
        mbar_init(mbV0, 1); mbar_init(mbV1, 1);
    }

    float aq[16][4];
    {
        int row0  = b*QQ + (g >> 2);
        int hq0   = kvh*GG + (g & 3);
        int row1  = b*QQ + ((g + 8) >> 2);
        int hq1   = kvh*GG + ((g + 8) & 3);
        const float* q0 = g_q + (size_t)row0*4096 + hq0*128;
        const float* q1 = g_q + (size_t)row1*4096 + hq1*128;
        #pragma unroll
        for (int ks = 0; ks < 16; ks++) {
            int kb = ks * 8;
            aq[ks][0] = tf32r(q0[kb + t]     * ATT_SCALE);
            aq[ks][1] = tf32r(q1[kb + t]     * ATT_SCALE);
            aq[ks][2] = tf32r(q0[kb + t + 4] * ATT_SCALE);
            aq[ks][3] = tf32r(q1[kb + t + 4] * ATT_SCALE);
        }
    }
    __syncthreads();

    float l0 = 0.f, l1 = 0.f;
    float oacc[16][4];
    #pragma unroll
    for (int nt = 0; nt < 16; nt++)
        #pragma unroll
        for (int j = 0; j < 4; j++) oacc[nt][j] = 0.f;

    int nch = (s1 - s0 + CH - 1) / CH;
    stage8(sm, mbK0, mbV0, 0, s0, cl, s1, b, kv0, cap, Kc, Vc, tid);

    for (int ci = 0; ci < nch; ci++) {
        int c0 = s0 + ci*CH;
        int bf = ci & 1;
        int par = (ci >> 1) & 1;

        if (ci + 1 < nch) {
            __syncthreads();
            stage8(sm, bf ? mbK0 : mbK1, bf ? mbV0 : mbV1, bf ^ 1,
                   c0 + CH, cl, s1, b, kv0, cap, Kc, Vc, tid);
        }

        mbar_wait(bf ? mbK1 : mbK0, par);

        float cA0 = 0.f, cA1 = 0.f, cA2 = 0.f, cA3 = 0.f;
        float cB0 = 0.f, cB1 = 0.f, cB2 = 0.f, cB3 = 0.f;
        {
            const float* Kb = sm + bf*STG_FLOATS + g*ROW_K + warp*128;
            #pragma unroll
            for (int ks = 0; ks < 16; ks += 2) {
                int kb = ks * 8;
                float b0 = Kb[kb + t];
                float b1 = Kb[kb + t + 4];
                mma_tf32(cA0, cA1, cA2, cA3,
                         aq[ks][0], aq[ks][1], aq[ks][2], aq[ks][3], b0, b1);
                float b2 = Kb[kb + 8 + t];
                float b3 = Kb[kb + 8 + t + 4];
                mma_tf32(cB0, cB1, cB2, cB3,
                         aq[ks+1][0], aq[ks+1][1], aq[ks+1][2], aq[ks+1][3], b2, b3);
            }
        }
        float c0r = cA0 + cB0, c1r = cA1 + cB1;
        float c2r = cA2 + cB2, c3r = cA3 + cB3;

        int Lg = min(s1, cl + (g >> 2) + 1) - c0;
        int Lh = min(s1, cl + ((g + 8) >> 2) + 1) - c0;
        int pc0 = 2*t, pc1 = 2*t + 1;

        float e00 = (pc0 < Lg) ? __expf(c0r) : 0.f;
        float e01 = (pc1 < Lg) ? __expf(c1r) : 0.f;
        float e10 = (pc0 < Lh) ? __expf(c2r) : 0.f;
        float e11 = (pc1 < Lh) ? __expf(c3r) : 0.f;

        l0 += e00 + e01;
        l1 += e10 + e11;

        e00 = tf32r(e00); e01 = tf32r(e01); e10 = tf32r(e10); e11 = tf32r(e11);

        int srcA = (g << 2) | (t >> 1);
        int srcB = srcA + 2;
        float f0a = __shfl_sync(0xffffffffu, e00, srcA);
        float f1a = __shfl_sync(0xffffffffu, e01, srcA);
        float f0b = __shfl_sync(0xffffffffu, e00, srcB);
        float f1b = __shfl_sync(0xffffffffu, e01, srcB);
        float h0a = __shfl_sync(0xffffffffu, e10, srcA);
        float h1a = __shfl_sync(0xffffffffu, e11, srcA);
        float h0b = __shfl_sync(0xffffffffu, e10, srcB);
        float h1b = __shfl_sync(0xffffffffu, e11, srcB);
        bool odd = (t & 1);
        float a0 = odd ? f1a : f0a;
        float a1 = odd ? h1a : h0a;
        float a2 = odd ? f1b : f0b;
        float a3 = odd ? h1b : h0b;

        mbar_wait(bf ? mbV1 : mbV0, par);

        {
            const float* Vb = sm + bf*STG_FLOATS + OFF_VS + warp*128;
            const float* Vr0 = Vb + t*ROW_V;
            const float* Vr1 = Vb + (t + 4)*ROW_V;
            #pragma unroll
            for (int nt = 0; nt < 16; nt++) {
                int n0 = nt*8 + g;
                float b0 = Vr0[n0];
                float b1 = Vr1[n0];
                mma_tf32(oacc[nt][0], oacc[nt][1], oacc[nt][2], oacc[nt][3],
                         a0, a1, a2, a3, b0, b1);
            }
        }
    }

    l0 += __shfl_xor_sync(0xffffffffu, l0, 1);
    l0 += __shfl_xor_sync(0xffffffffu, l0, 2);
    l1 += __shfl_xor_sync(0xffffffffu, l1, 1);
    l1 += __shfl_xor_sync(0xffffffffu, l1, 2);

    #pragma unroll
    for (int nt = 0; nt < 16; nt++) {
        int col = nt*8 + 2*t;
        *(float2*)(g_po + (pbase + g    )*HD + col) = make_float2(oacc[nt][0], oacc[nt][1]);
        *(float2*)(g_po + (pbase + g + 8)*HD + col) = make_float2(oacc[nt][2], oacc[nt][3]);
    }
    if (t == 0) {
        g_pml[(pbase + g)*2]          = 0.f;
        g_pml[(pbase + g)*2 + 1]      = l0;
        g_pml[(pbase + g + 8)*2]      = 0.f;
        g_pml[(pbase + g + 8)*2 + 1]  = l1;
    }
}

// ---------------- 5. combine: plain sums (fixed-max => no exp), wide grid ----------------
// 1024 rows (b,kv,qi) x 32 float4-groups = 32768 threads = 128 blocks x 256.
// Warp = one row, 32 consecutive float4 -> fully coalesced 512B loads per split.
__global__ void k_combine() {
    int gid = blockIdx.x * 256 + threadIdx.x;
    int row = gid >> 5;                   // (bkv, qi)
    int dgp = gid & 31;
    int d0  = dgp * 4;
    int bkv = row >> 4;
    int qi  = row & 15;
    int b   = bkv >> 3, kv = bkv & 7;
    size_t base = ((size_t)bkv * NSPLIT + 0) * 16 + qi;

    float l_tot = 0.f;
    float4 o = make_float4(0.f, 0.f, 0.f, 0.f);
    #pragma unroll 1
    for (int s = 0; s < NSPLIT; s++) {
        size_t idx = base + (size_t)s * 16;
        l_tot += g_pml[idx*2 + 1];
        float4 x = *(const float4*)(g_po + idx*HD + d0);
        o.x += x.x; o.y += x.y; o.z += x.z; o.w += x.w;
    }
    float inv = 1.f / l_tot;
    int qo = qi >> 2, g = qi & 3;
    int tok  = b*QQ + qo;
    int head = kv*GG + g;
    size_t cbase = (size_t)(head*128 + d0)*NTOK + tok;
    g_attnT[cbase]          = tf32r(o.x * inv);
    g_attnT[cbase + NTOK]   = tf32r(o.y * inv);
    g_attnT[cbase + 2*NTOK] = tf32r(o.z * inv);
    g_attnT[cbase + 3*NTOK] = tf32r(o.w * inv);
}

// ---------------- 6. O GEMM (tf32 mma, K-split) ----------------
__global__ void __launch_bounds__(128) k_gemm_o(const float* __restrict__ Wo) {
    extern __shared__ float gsm[];
    int colbase = blockIdx.x * 128;
    float* outb = g_part_out + (size_t)blockIdx.y * NTOK * HH;
    gemm_body(g_attnT, Wo, 4096, colbase, blockIdx.y * GKRANGE,
              outb, HH, colbase, gsm);
}

// ---------------- 7. reduce O partials -> output ----------------
__global__ void k_reduce_out(float* __restrict__ out) {
    int idx = blockIdx.x * 256 + threadIdx.x;
    float s = 0.f;
    #pragma unroll
    for (int i = 0; i < GSPLIT; i++)
        s += g_part_out[(size_t)i * NTOK * HH + idx];
    out[idx] = s;
}

// ---------------- launch ----------------
extern "C" void kernel_launch(void* const* d_in, const int* in_sizes, int n_in,
                              void* d_out, int out_size) {
    const float* hidden = (const float*)d_in[0];
    const float* cosb   = (const float*)d_in[1];
    const float* sinb   = (const float*)d_in[2];
    const float* Wq     = (const float*)d_in[3];
    const float* Wk     = (const float*)d_in[4];
    const float* Wv     = (const float*)d_in[5];
    const float* Wo     = (const float*)d_in[6];
    const float* Kc     = (const float*)d_in[7];
    const float* Vc     = (const float*)d_in[8];
    const int*   cls    = (const int*)d_in[9];
    int cap = in_sizes[7] / (BB * NKV * HD);   // 4100

    static int attr_set = 0;
    if (!attr_set) {
        cudaFuncSetAttribute(k_attn, cudaFuncAttributeMaxDynamicSharedMemorySize,
                             SMEM_ATTN_BYTES);
        cudaFuncSetAttribute(k_gemm_qkv, cudaFuncAttributeMaxDynamicSharedMemorySize,
                             GSMEM_BYTES);
        cudaFuncSetAttribute(k_gemm_o, cudaFuncAttributeMaxDynamicSharedMemorySize,
                             GSMEM_BYTES);
        attr_set = 1;
    }

    k_transpose  <<<512, 256>>>(hidden);
    k_gemm_qkv   <<<dim3(48, GSPLIT), 128, GSMEM_BYTES>>>(Wq, Wk, Wv);
    k_reduce_rope<<<dim3(48, NTOK), 128>>>(cosb, sinb);
    k_attn       <<<dim3(NSPLIT, 2, BB), 128, SMEM_ATTN_BYTES>>>(Kc, Vc, cls, cap);
    k_combine    <<<128, 256>>>();
    k_gemm_o     <<<dim3(32, GSPLIT), 128, GSMEM_BYTES>>>(Wo);
    k_reduce_out <<<512, 256>>>((float*)d_out);
}

// round 14
// speedup vs baseline: 1.0605x; 1.0385x over previous
#include <cuda_runtime.h>
#include <math.h>

#define BB 8
#define QQ 4
#define HH 4096
#define NHEAD 32
#define NKV 8
#define HD 128
#define GG 4
#define NTOK (BB*QQ)                     // 32
#define QKV_COLS (NHEAD*HD + 2*NKV*HD)   // 6144
#define NSPLIT 27
#define ATT_SCALE 0.08838834764831845f   // 1/sqrt(128)

// ---- attention smem layout (floats), 2-stage pipeline (R9 config) ----
#define CH 8
#define ROW_K 516
#define ROW_V 520
#define OFF_VS (CH*ROW_K)                 // 4128
#define STG_FLOATS (CH*ROW_K + CH*ROW_V)  // 8288
#define OFF_MB_A (2*STG_FLOATS)           // 16576
#define SMEM_ATTN_BYTES (OFF_MB_A*4 + 32) // 66336

// ---- tensor-core GEMM config ----
#define GSPLIT 16
#define GKRANGE (HH/GSPLIT)               // 256
#define GK 32                             // 45KB smem -> 5 blocks/SM
#define GNCH (GKRANGE/GK)                 // 8
#define GPAD_A 40
#define GPAD_B 136
#define GOFF_B (2*GK*GPAD_A)              // 2560 floats
#define GSMEM_FLOATS (GOFF_B + 2*GK*GPAD_B)   // 11264
#define GSMEM_BYTES (GSMEM_FLOATS*4)          // 45056

// ---------------- device scratch ----------------
__device__ float g_hT[HH*NTOK];
__device__ float g_part_qkv[GSPLIT*NTOK*QKV_COLS];
__device__ float g_q[NTOK*NHEAD*HD];
__device__ float g_k[NTOK*NKV*HD];
__device__ float g_v[NTOK*NKV*HD];
__device__ float g_po[BB*NKV*NSPLIT*16*HD];
__device__ float g_pml[BB*NKV*NSPLIT*16*2];
__device__ float g_attnT[HH*NTOK];
__device__ float g_part_out[GSPLIT*NTOK*HH];

// ---------------- tf32 / mma helpers ----------------
__device__ __forceinline__ float tf32r(float x) {
    unsigned u;
    asm("cvt.rna.tf32.f32 %0, %1;" : "=r"(u) : "f"(x));
    return __uint_as_float(u);
}
__device__ __forceinline__ void mma_tf32(float& d0, float& d1, float& d2, float& d3,
                                         float a0, float a1, float a2, float a3,
                                         float b0, float b1) {
    asm volatile(
        "mma.sync.aligned.m16n8k8.row.col.f32.tf32.tf32.f32 "
        "{%0,%1,%2,%3}, {%4,%5,%6,%7}, {%8,%9}, {%0,%1,%2,%3};"
        : "+f"(d0), "+f"(d1), "+f"(d2), "+f"(d3)
        : "r"(__float_as_uint(a0)), "r"(__float_as_uint(a1)),
          "r"(__float_as_uint(a2)), "r"(__float_as_uint(a3)),
          "r"(__float_as_uint(b0)), "r"(__float_as_uint(b1)));
}

// ---------------- mbarrier / bulk / cp.async helpers ----------------
__device__ __forceinline__ unsigned smem_u32(const void* p) {
    return (unsigned)__cvta_generic_to_shared(p);
}
__device__ __forceinline__ void mbar_init(unsigned mbar, unsigned count) {
    asm volatile("mbarrier.init.shared.b64 [%0], %1;" :: "r"(mbar), "r"(count) : "memory");
}
__device__ __forceinline__ void mbar_expect_tx(unsigned mbar, unsigned tx) {
    asm volatile("mbarrier.arrive.expect_tx.shared.b64 _, [%0], %1;"
                 :: "r"(mbar), "r"(tx) : "memory");
}
__device__ __forceinline__ void mbar_wait(unsigned mbar, int parity) {
    asm volatile(
        "{\n\t.reg .pred P;\n\t"
        "W_%=:\n\t"
        "mbarrier.try_wait.parity.acquire.cta.shared::cta.b64 P, [%0], %1, 0x989680;\n\t"
        "@P bra.uni D_%=;\n\t"
        "bra.uni W_%=;\n\t"
        "D_%=:\n\t}"
        :: "r"(mbar), "r"(parity) : "memory");
}
__device__ __forceinline__ void bulk_cp(unsigned dst, const void* src, unsigned bytes,
                                        unsigned mbar) {
    asm volatile(
        "cp.async.bulk.shared::cta.global.mbarrier::complete_tx::bytes [%0], [%1], %2, [%3];"
        :: "r"(dst), "l"(src), "r"(bytes), "r"(mbar) : "memory");
}
__device__ __forceinline__ void cp16(float* dstp, const float* src) {
    unsigned d = (unsigned)__cvta_generic_to_shared(dstp);
    asm volatile("cp.async.cg.shared.global [%0], [%1], 16;" :: "r"(d), "l"(src));
}
#define CP_COMMIT() asm volatile("cp.async.commit_group;")

// ---------------- 1. transpose hidden (pre-round to tf32) ----------------
__global__ void k_transpose(const float* __restrict__ x) {
    int idx = blockIdx.x * 256 + threadIdx.x;
    int r = idx >> 12;
    int k = idx & 4095;
    g_hT[k*NTOK + r] = tf32r(x[idx]);
}

// ---------------- shared tensor-core GEMM body (cp.async A staging) ----------------
__device__ __forceinline__ void gemm_body(const float* __restrict__ Asrc,
                                          const float* __restrict__ Wsrc,
                                          int wstride, int cb, int k0base,
                                          float* __restrict__ outb, int ostride,
                                          int colbase, float* gsm) {
    float* hA = gsm;
    float* wB = gsm + GOFF_B;
    int tid  = threadIdx.x;
    int warp = tid >> 5;
    int lane = tid & 31;
    int g    = lane >> 2;
    int t    = lane & 3;

    float c[2][4][4];
    #pragma unroll
    for (int m = 0; m < 2; m++)
        #pragma unroll
        for (int j = 0; j < 4; j++)
            #pragma unroll
            for (int v = 0; v < 4; v++) c[m][j][v] = 0.f;

    auto stage = [&](int buf, int kc) {
        int k0 = k0base + kc*GK;
        #pragma unroll
        for (int i = 0; i < 2; i++) {
            int idx = tid + i*128;
            int r = idx >> 3, c4 = idx & 7;
            cp16(hA + buf*GK*GPAD_A + r*GPAD_A + c4*4,
                 Asrc + (size_t)(k0 + r)*NTOK + c4*4);
        }
        #pragma unroll
        for (int i = 0; i < 8; i++) {
            int idx = tid + i*128;
            int r = idx >> 5, c4 = idx & 31;
            cp16(wB + buf*GK*GPAD_B + r*GPAD_B + c4*4,
                 Wsrc + (size_t)(k0 + r)*wstride + cb + c4*4);
        }
    };

    stage(0, 0);
    CP_COMMIT();

    for (int kc = 0; kc < GNCH; kc++) {
        int buf = kc & 1;
        if (kc + 1 < GNCH) {
            stage(buf ^ 1, kc + 1);
            CP_COMMIT();
            asm volatile("cp.async.wait_group 1;");
        } else {
            asm volatile("cp.async.wait_group 0;");
        }
        __syncthreads();

        const float* hb = hA + buf*GK*GPAD_A;
        const float* wb = wB + buf*GK*GPAD_B;
        #pragma unroll
        for (int ks = 0; ks < GK/8; ks++) {
            int kb = ks * 8;
            float a[2][4];
            #pragma unroll
            for (int m = 0; m < 2; m++) {
                int m0 = m*16;
                a[m][0] = hb[(kb+t)*GPAD_A   + m0 + g];
                a[m][1] = hb[(kb+t)*GPAD_A   + m0 + g + 8];
                a[m][2] = hb[(kb+t+4)*GPAD_A + m0 + g];
                a[m][3] = hb[(kb+t+4)*GPAD_A + m0 + g + 8];
            }
            #pragma unroll
            for (int j = 0; j < 4; j++) {
                int n = warp*32 + j*8 + g;
                float b0 = tf32r(wb[(kb+t)*GPAD_B   + n]);
                float b1 = tf32r(wb[(kb+t+4)*GPAD_B + n]);
                mma_tf32(c[0][j][0], c[0][j][1], c[0][j][2], c[0][j][3],
                         a[0][0], a[0][1], a[0][2], a[0][3], b0, b1);
                mma_tf32(c[1][j][0], c[1][j][1], c[1][j][2], c[1][j][3],
                         a[1][0], a[1][1], a[1][2], a[1][3], b0, b1);
            }
        }
        __syncthreads();
    }

    #pragma unroll
    for (int m = 0; m < 2; m++)
        #pragma unroll
        for (int j = 0; j < 4; j++) {
            int col = colbase + warp*32 + j*8 + 2*t;
            int r0  = m*16 + g;
            *(float2*)&outb[(size_t)r0*ostride + col] =
                make_float2(c[m][j][0], c[m][j][1]);
            *(float2*)&outb[(size_t)(r0+8)*ostride + col] =
                make_float2(c[m][j][2], c[m][j][3]);
        }
}

// ---------------- 2. QKV GEMM (tf32 mma, K-split 16) ----------------
__global__ void __launch_bounds__(128) k_gemm_qkv(const float* __restrict__ Wq,
                                                  const float* __restrict__ Wk,
                                                  const float* __restrict__ Wv) {
    extern __shared__ float gsm[];
    int colbase = blockIdx.x * 128;
    const float* Wsrc; int wstride, cb;
    if (colbase < 4096)       { Wsrc = Wq; wstride = 4096; cb = colbase; }
    else if (colbase < 5120)  { Wsrc = Wk; wstride = 1024; cb = colbase - 4096; }
    else                      { Wsrc = Wv; wstride = 1024; cb = colbase - 5120; }
    float* outb = g_part_qkv + (size_t)blockIdx.y * NTOK * QKV_COLS;
    gemm_body(g_hT, Wsrc, wstride, cb, blockIdx.y * GKRANGE,
              outb, QKV_COLS, colbase, gsm);
}

// ---------------- 3. reduce K-splits + RoPE ----------------
__global__ void k_reduce_rope(const float* __restrict__ cosb,
                              const float* __restrict__ sinb) {
    int slot = blockIdx.x;
    int row  = blockIdx.y;
    int d    = threadIdx.x;
    int col  = slot*128 + d;

    float s = 0.f;
    #pragma unroll
    for (int i = 0; i < GSPLIT; i++)
        s += g_part_qkv[((size_t)i*NTOK + row)*QKV_COLS + col];

    __shared__ float x[128];
    x[d] = s;
    __syncthreads();

    if (slot < 40) {
        float c  = cosb[row*128 + d];
        float sn = sinb[row*128 + d];
        float rot = (d < 64) ? -x[d + 64] : x[d - 64];
        float val = s*c + rot*sn;
        if (slot < 32) g_q[(size_t)row*4096 + col] = val;
        else           g_k[(size_t)row*1024 + (slot-32)*128 + d] = val;
    } else {
        g_v[(size_t)row*1024 + (slot-40)*128 + d] = s;
    }
}

// ---------------- 4. attention: R9 config (2-stage, 4 heads/block, 2KB TMA) ----------------
__device__ __forceinline__ void stage8(float* sm, unsigned mbK, unsigned mbV,
        int stg, int c0, int cl, int s1, int b, int kv0, int cap,
        const float* Kc, const float* Vc, int tid) {
    int nv = min(CH, s1 - c0);
    if (tid == 0) {
        mbar_expect_tx(mbK, (unsigned)nv * 2048u);
        mbar_expect_tx(mbV, (unsigned)nv * 2048u);
    }
    if (tid < 16) {
        int p = tid & 7;
        if (p < nv) {
            int sg = c0 + p;
            bool isV = tid >= 8;
            const float* src;
            if (sg < cl) {
                src = (isV ? Vc : Kc) + (((size_t)b*cap + sg)*NKV + kv0)*HD;
            } else {
                int row = b*QQ + (sg - cl);
                src = (isV ? g_v : g_k) + ((size_t)row*(NKV*HD) + kv0*HD);
            }
            float* dstp = sm + stg*STG_FLOATS + (isV ? OFF_VS + p*ROW_V : p*ROW_K);
            bulk_cp(smem_u32(dstp), src, 2048u, isV ? mbV : mbK);
        }
    }
}

__global__ void __launch_bounds__(128, 3) k_attn(const float* __restrict__ Kc,
                       const float* __restrict__ Vc,
                       const int* __restrict__ cache_lens, int cap) {
    extern __shared__ float sm[];
    unsigned mbb  = smem_u32(sm + OFF_MB_A);
    unsigned mbK0 = mbb,       mbK1 = mbb + 8;
    unsigned mbV0 = mbb + 16,  mbV1 = mbb + 24;

    int tid  = threadIdx.x;
    int warp = tid >> 5;
    int lane = tid & 31;
    int g    = lane >> 2;
    int t    = lane & 3;

    int split = blockIdx.x;
    int kv0   = blockIdx.y * 4;
    int b     = blockIdx.z;
    int kvh   = kv0 + warp;

    int cl = cache_lens[b];
    int n_total = cl + QQ;
    int len = (n_total + NSPLIT - 1) / NSPLIT;
    int s0 = split * len;
    int s1 = min(s0 + len, n_total);
    size_t pbase = (((size_t)(b*NKV + kvh))*NSPLIT + split)*16;

    if (s0 >= s1) {
        if (lane < 16) {
            g_pml[(pbase + lane)*2]     = 0.f;
            g_pml[(pbase + lane)*2 + 1] = 0.f;
        }
        for (int i = lane; i < 16*HD; i += 32)
            g_po[pbase*HD + i] = 0.f;
        return;
    }

    if (tid == 0) {
        mbar_init(mbK0, 1); mbar_init(mbK1, 1);
        mbar_init(mbV0, 1); mbar_init(mbV1, 1);
    }

    float aq[16][4];
    {
        int row0  = b*QQ + (g >> 2);
        int hq0   = kvh*GG + (g & 3);
        int row1  = b*QQ + ((g + 8) >> 2);
        int hq1   = kvh*GG + ((g + 8) & 3);
        const float* q0 = g_q + (size_t)row0*4096 + hq0*128;
        const float* q1 = g_q + (size_t)row1*4096 + hq1*128;
        #pragma unroll
        for (int ks = 0; ks < 16; ks++) {
            int kb = ks * 8;
            aq[ks][0] = tf32r(q0[kb + t]     * ATT_SCALE);
            aq[ks][1] = tf32r(q1[kb + t]     * ATT_SCALE);
            aq[ks][2] = tf32r(q0[kb + t + 4] * ATT_SCALE);
            aq[ks][3] = tf32r(q1[kb + t + 4] * ATT_SCALE);
        }
    }
    __syncthreads();

    float l0 = 0.f, l1 = 0.f;
    float oacc[16][4];
    #pragma unroll
    for (int nt = 0; nt < 16; nt++)
        #pragma unroll
        for (int j = 0; j < 4; j++) oacc[nt][j] = 0.f;

    int nch = (s1 - s0 + CH - 1) / CH;
    stage8(sm, mbK0, mbV0, 0, s0, cl, s1, b, kv0, cap, Kc, Vc, tid);

    for (int ci = 0; ci < nch; ci++) {
        int c0 = s0 + ci*CH;
        int bf = ci & 1;
        int par = (ci >> 1) & 1;

        if (ci + 1 < nch) {
            __syncthreads();
            stage8(sm, bf ? mbK0 : mbK1, bf ? mbV0 : mbV1, bf ^ 1,
                   c0 + CH, cl, s1, b, kv0, cap, Kc, Vc, tid);
        }

        mbar_wait(bf ? mbK1 : mbK0, par);

        float cA0 = 0.f, cA1 = 0.f, cA2 = 0.f, cA3 = 0.f;
        float cB0 = 0.f, cB1 = 0.f, cB2 = 0.f, cB3 = 0.f;
        {
            const float* Kb = sm + bf*STG_FLOATS + g*ROW_K + warp*128;
            #pragma unroll
            for (int ks = 0; ks < 16; ks += 2) {
                int kb = ks * 8;
                float b0 = Kb[kb + t];
                float b1 = Kb[kb + t + 4];
                mma_tf32(cA0, cA1, cA2, cA3,
                         aq[ks][0], aq[ks][1], aq[ks][2], aq[ks][3], b0, b1);
                float b2 = Kb[kb + 8 + t];
                float b3 = Kb[kb + 8 + t + 4];
                mma_tf32(cB0, cB1, cB2, cB3,
                         aq[ks+1][0], aq[ks+1][1], aq[ks+1][2], aq[ks+1][3], b2, b3);
            }
        }
        float c0r = cA0 + cB0, c1r = cA1 + cB1;
        float c2r = cA2 + cB2, c3r = cA3 + cB3;

        int Lg = min(s1, cl + (g >> 2) + 1) - c0;
        int Lh = min(s1, cl + ((g + 8) >> 2) + 1) - c0;
        int pc0 = 2*t, pc1 = 2*t + 1;

        float e00 = (pc0 < Lg) ? __expf(c0r) : 0.f;
        float e01 = (pc1 < Lg) ? __expf(c1r) : 0.f;
        float e10 = (pc0 < Lh) ? __expf(c2r) : 0.f;
        float e11 = (pc1 < Lh) ? __expf(c3r) : 0.f;

        l0 += e00 + e01;
        l1 += e10 + e11;

        e00 = tf32r(e00); e01 = tf32r(e01); e10 = tf32r(e10); e11 = tf32r(e11);

        int srcA = (g << 2) | (t >> 1);
        int srcB = srcA + 2;
        float f0a = __shfl_sync(0xffffffffu, e00, srcA);
        float f1a = __shfl_sync(0xffffffffu, e01, srcA);
        float f0b = __shfl_sync(0xffffffffu, e00, srcB);
        float f1b = __shfl_sync(0xffffffffu, e01, srcB);
        float h0a = __shfl_sync(0xffffffffu, e10, srcA);
        float h1a = __shfl_sync(0xffffffffu, e11, srcA);
        float h0b = __shfl_sync(0xffffffffu, e10, srcB);
        float h1b = __shfl_sync(0xffffffffu, e11, srcB);
        bool odd = (t & 1);
        float a0 = odd ? f1a : f0a;
        float a1 = odd ? h1a : h0a;
        float a2 = odd ? f1b : f0b;
        float a3 = odd ? h1b : h0b;

        mbar_wait(bf ? mbV1 : mbV0, par);

        {
            const float* Vb = sm + bf*STG_FLOATS + OFF_VS + warp*128;
            const float* Vr0 = Vb + t*ROW_V;
            const float* Vr1 = Vb + (t + 4)*ROW_V;
            #pragma unroll
            for (int nt = 0; nt < 16; nt++) {
                int n0 = nt*8 + g;
                float b0 = Vr0[n0];
                float b1 = Vr1[n0];
                mma_tf32(oacc[nt][0], oacc[nt][1], oacc[nt][2], oacc[nt][3],
                         a0, a1, a2, a3, b0, b1);
            }
        }
    }

    l0 += __shfl_xor_sync(0xffffffffu, l0, 1);
    l0 += __shfl_xor_sync(0xffffffffu, l0, 2);
    l1 += __shfl_xor_sync(0xffffffffu, l1, 1);
    l1 += __shfl_xor_sync(0xffffffffu, l1, 2);

    #pragma unroll
    for (int nt = 0; nt < 16; nt++) {
        int col = nt*8 + 2*t;
        *(float2*)(g_po + (pbase + g    )*HD + col) = make_float2(oacc[nt][0], oacc[nt][1]);
        *(float2*)(g_po + (pbase + g + 8)*HD + col) = make_float2(oacc[nt][2], oacc[nt][3]);
    }
    if (t == 0) {
        g_pml[(pbase + g)*2]          = 0.f;
        g_pml[(pbase + g)*2 + 1]      = l0;
        g_pml[(pbase + g + 8)*2]      = 0.f;
        g_pml[(pbase + g + 8)*2 + 1]  = l1;
    }
}

// ---------------- 5. combine: plain sums (fixed-max => no exp), wide grid ----------------
__global__ void k_combine() {
    int gid = blockIdx.x * 256 + threadIdx.x;
    int row = gid >> 5;
    int dgp = gid & 31;
    int d0  = dgp * 4;
    int bkv = row >> 4;
    int qi  = row & 15;
    int b   = bkv >> 3, kv = bkv & 7;
    size_t base = (size_t)bkv * NSPLIT * 16 + qi;

    float l_tot = 0.f;
    float4 o = make_float4(0.f, 0.f, 0.f, 0.f);
    #pragma unroll
    for (int s = 0; s < NSPLIT; s++) {
        size_t idx = base + (size_t)s * 16;
        l_tot += g_pml[idx*2 + 1];
        float4 x = *(const float4*)(g_po + idx*HD + d0);
        o.x += x.x; o.y += x.y; o.z += x.z; o.w += x.w;
    }
    float inv = 1.f / l_tot;
    int qo = qi >> 2, g = qi & 3;
    int tok  = b*QQ + qo;
    int head = kv*GG + g;
    size_t cbase = (size_t)(head*128 + d0)*NTOK + tok;
    g_attnT[cbase]          = tf32r(o.x * inv);
    g_attnT[cbase + NTOK]   = tf32r(o.y * inv);
    g_attnT[cbase + 2*NTOK] = tf32r(o.z * inv);
    g_attnT[cbase + 3*NTOK] = tf32r(o.w * inv);
}

// ---------------- 6. O GEMM (tf32 mma, K-split 16) ----------------
__global__ void __launch_bounds__(128) k_gemm_o(const float* __restrict__ Wo) {
    extern __shared__ float gsm[];
    int colbase = blockIdx.x * 128;
    float* outb = g_part_out + (size_t)blockIdx.y * NTOK * HH;
    gemm_body(g_attnT, Wo, 4096, colbase, blockIdx.y * GKRANGE,
              outb, HH, colbase, gsm);
}

// ---------------- 7. reduce O partials -> output ----------------
__global__ void k_reduce_out(float* __restrict__ out) {
    int idx = blockIdx.x * 256 + threadIdx.x;
    float s = 0.f;
    #pragma unroll
    for (int i = 0; i < GSPLIT; i++)
        s += g_part_out[(size_t)i * NTOK * HH + idx];
    out[idx] = s;
}

// ---------------- launch ----------------
extern "C" void kernel_launch(void* const* d_in, const int* in_sizes, int n_in,
                              void* d_out, int out_size) {
    const float* hidden = (const float*)d_in[0];
    const float* cosb   = (const float*)d_in[1];
    const float* sinb   = (const float*)d_in[2];
    const float* Wq     = (const float*)d_in[3];
    const float* Wk     = (const float*)d_in[4];
    const float* Wv     = (const float*)d_in[5];
    const float* Wo     = (const float*)d_in[6];
    const float* Kc     = (const float*)d_in[7];
    const float* Vc     = (const float*)d_in[8];
    const int*   cls    = (const int*)d_in[9];
    int cap = in_sizes[7] / (BB * NKV * HD);   // 4100

    static int attr_set = 0;
    if (!attr_set) {
        cudaFuncSetAttribute(k_attn, cudaFuncAttributeMaxDynamicSharedMemorySize,
                             SMEM_ATTN_BYTES);
        cudaFuncSetAttribute(k_gemm_qkv, cudaFuncAttributeMaxDynamicSharedMemorySize,
                             GSMEM_BYTES);
        cudaFuncSetAttribute(k_gemm_o, cudaFuncAttributeMaxDynamicSharedMemorySize,
                             GSMEM_BYTES);
        attr_set = 1;
    }

    k_transpose  <<<512, 256>>>(hidden);
    k_gemm_qkv   <<<dim3(48, GSPLIT), 128, GSMEM_BYTES>>>(Wq, Wk, Wv);
    k_reduce_rope<<<dim3(48, NTOK), 128>>>(cosb, sinb);
    k_attn       <<<dim3(NSPLIT, 2, BB), 128, SMEM_ATTN_BYTES>>>(Kc, Vc, cls, cap);
    k_combine    <<<128, 256>>>();
    k_gemm_o     <<<dim3(32, GSPLIT), 128, GSMEM_BYTES>>>(Wo);
    k_reduce_out <<<512, 256>>>((float*)d_out);
}

// round 15
// speedup vs baseline: 1.0837x; 1.0219x over previous
#include <cuda_runtime.h>
#include <math.h>

#define BB 8
#define QQ 4
#define HH 4096
#define NHEAD 32
#define NKV 8
#define HD 128
#define GG 4
#define NTOK (BB*QQ)                     // 32
#define QKV_COLS (NHEAD*HD + 2*NKV*HD)   // 6144
#define NSPLIT 27
#define ATT_SCALE 0.08838834764831845f   // 1/sqrt(128)

// ---- attention smem layout (floats), 2-stage pipeline (R9 config) ----
#define CH 8
#define ROW_K 516
#define ROW_V 520
#define OFF_VS (CH*ROW_K)                 // 4128
#define STG_FLOATS (CH*ROW_K + CH*ROW_V)  // 8288
#define OFF_MB_A (2*STG_FLOATS)           // 16576
#define SMEM_ATTN_BYTES (OFF_MB_A*4 + 32) // 66336

// ---- tensor-core GEMM config: 64-wide N blocks, K-split 8 ----
#define GSPLIT 8
#define GKRANGE (HH/GSPLIT)               // 512
#define GK 32
#define GNCH (GKRANGE/GK)                 // 16
#define GNB 64                            // columns per block
#define GPAD_A 40
#define GPAD_B 72                         // 64 + 8 pad (stride%32==8)
#define GOFF_B (2*GK*GPAD_A)              // 2560 floats
#define GSMEM_FLOATS (GOFF_B + 2*GK*GPAD_B)   // 7168
#define GSMEM_BYTES (GSMEM_FLOATS*4)          // 28672

// ---------------- device scratch ----------------
__device__ float g_hT[HH*NTOK];
__device__ float g_part_qkv[GSPLIT*NTOK*QKV_COLS];
__device__ float g_q[NTOK*NHEAD*HD];
__device__ float g_k[NTOK*NKV*HD];
__device__ float g_v[NTOK*NKV*HD];
__device__ float g_po[BB*NKV*NSPLIT*16*HD];
__device__ float g_pml[BB*NKV*NSPLIT*16*2];
__device__ float g_attnT[HH*NTOK];
__device__ float g_part_out[GSPLIT*NTOK*HH];

// ---------------- tf32 / mma helpers ----------------
__device__ __forceinline__ float tf32r(float x) {
    unsigned u;
    asm("cvt.rna.tf32.f32 %0, %1;" : "=r"(u) : "f"(x));
    return __uint_as_float(u);
}
__device__ __forceinline__ void mma_tf32(float& d0, float& d1, float& d2, float& d3,
                                         float a0, float a1, float a2, float a3,
                                         float b0, float b1) {
    asm volatile(
        "mma.sync.aligned.m16n8k8.row.col.f32.tf32.tf32.f32 "
        "{%0,%1,%2,%3}, {%4,%5,%6,%7}, {%8,%9}, {%0,%1,%2,%3};"
        : "+f"(d0), "+f"(d1), "+f"(d2), "+f"(d3)
        : "r"(__float_as_uint(a0)), "r"(__float_as_uint(a1)),
          "r"(__float_as_uint(a2)), "r"(__float_as_uint(a3)),
          "r"(__float_as_uint(b0)), "r"(__float_as_uint(b1)));
}

// ---------------- mbarrier / bulk / cp.async helpers ----------------
__device__ __forceinline__ unsigned smem_u32(const void* p) {
    return (unsigned)__cvta_generic_to_shared(p);
}
__device__ __forceinline__ void mbar_init(unsigned mbar, unsigned count) {
    asm volatile("mbarrier.init.shared.b64 [%0], %1;" :: "r"(mbar), "r"(count) : "memory");
}
__device__ __forceinline__ void mbar_expect_tx(unsigned mbar, unsigned tx) {
    asm volatile("mbarrier.arrive.expect_tx.shared.b64 _, [%0], %1;"
                 :: "r"(mbar), "r"(tx) : "memory");
}
__device__ __forceinline__ void mbar_wait(unsigned mbar, int parity) {
    asm volatile(
        "{\n\t.reg .pred P;\n\t"
        "W_%=:\n\t"
        "mbarrier.try_wait.parity.acquire.cta.shared::cta.b64 P, [%0], %1, 0x989680;\n\t"
        "@P bra.uni D_%=;\n\t"
        "bra.uni W_%=;\n\t"
        "D_%=:\n\t}"
        :: "r"(mbar), "r"(parity) : "memory");
}
__device__ __forceinline__ void bulk_cp(unsigned dst, const void* src, unsigned bytes,
                                        unsigned mbar) {
    asm volatile(
        "cp.async.bulk.shared::cta.global.mbarrier::complete_tx::bytes [%0], [%1], %2, [%3];"
        :: "r"(dst), "l"(src), "r"(bytes), "r"(mbar) : "memory");
}
__device__ __forceinline__ void cp16(float* dstp, const float* src) {
    unsigned d = (unsigned)__cvta_generic_to_shared(dstp);
    asm volatile("cp.async.cg.shared.global [%0], [%1], 16;" :: "r"(d), "l"(src));
}
#define CP_COMMIT() asm volatile("cp.async.commit_group;")

// ---------------- 1. transpose hidden (pre-round to tf32) ----------------
__global__ void k_transpose(const float* __restrict__ x) {
    int idx = blockIdx.x * 256 + threadIdx.x;
    int r = idx >> 12;
    int k = idx & 4095;
    g_hT[k*NTOK + r] = tf32r(x[idx]);
}

// ---------------- shared tensor-core GEMM body (64-wide N, cp.async) ----------------
__device__ __forceinline__ void gemm_body(const float* __restrict__ Asrc,
                                          const float* __restrict__ Wsrc,
                                          int wstride, int cb, int k0base,
                                          float* __restrict__ outb, int ostride,
                                          int colbase, float* gsm) {
    float* hA = gsm;
    float* wB = gsm + GOFF_B;
    int tid  = threadIdx.x;
    int warp = tid >> 5;
    int lane = tid & 31;
    int g    = lane >> 2;
    int t    = lane & 3;

    float c[2][2][4];
    #pragma unroll
    for (int m = 0; m < 2; m++)
        #pragma unroll
        for (int j = 0; j < 2; j++)
            #pragma unroll
            for (int v = 0; v < 4; v++) c[m][j][v] = 0.f;

    auto stage = [&](int buf, int kc) {
        int k0 = k0base + kc*GK;
        #pragma unroll
        for (int i = 0; i < 2; i++) {          // A: 32 rows x 32 floats
            int idx = tid + i*128;
            int r = idx >> 3, c4 = idx & 7;
            cp16(hA + buf*GK*GPAD_A + r*GPAD_A + c4*4,
                 Asrc + (size_t)(k0 + r)*NTOK + c4*4);
        }
        #pragma unroll
        for (int i = 0; i < 4; i++) {          // W: 32 rows x 64 floats
            int idx = tid + i*128;
            int r = idx >> 4, c4 = idx & 15;
            cp16(wB + buf*GK*GPAD_B + r*GPAD_B + c4*4,
                 Wsrc + (size_t)(k0 + r)*wstride + cb + c4*4);
        }
    };

    stage(0, 0);
    CP_COMMIT();

    for (int kc = 0; kc < GNCH; kc++) {
        int buf = kc & 1;
        if (kc + 1 < GNCH) {
            stage(buf ^ 1, kc + 1);
            CP_COMMIT();
            asm volatile("cp.async.wait_group 1;");
        } else {
            asm volatile("cp.async.wait_group 0;");
        }
        __syncthreads();

        const float* hb = hA + buf*GK*GPAD_A;
        const float* wb = wB + buf*GK*GPAD_B;
        #pragma unroll
        for (int ks = 0; ks < GK/8; ks++) {
            int kb = ks * 8;
            float a[2][4];
            #pragma unroll
            for (int m = 0; m < 2; m++) {
                int m0 = m*16;
                a[m][0] = hb[(kb+t)*GPAD_A   + m0 + g];
                a[m][1] = hb[(kb+t)*GPAD_A   + m0 + g + 8];
                a[m][2] = hb[(kb+t+4)*GPAD_A + m0 + g];
                a[m][3] = hb[(kb+t+4)*GPAD_A + m0 + g + 8];
            }
            #pragma unroll
            for (int j = 0; j < 2; j++) {
                int n = warp*16 + j*8 + g;
                float b0 = tf32r(wb[(kb+t)*GPAD_B   + n]);
                float b1 = tf32r(wb[(kb+t+4)*GPAD_B + n]);
                mma_tf32(c[0][j][0], c[0][j][1], c[0][j][2], c[0][j][3],
                         a[0][0], a[0][1], a[0][2], a[0][3], b0, b1);
                mma_tf32(c[1][j][0], c[1][j][1], c[1][j][2], c[1][j][3],
                         a[1][0], a[1][1], a[1][2], a[1][3], b0, b1);
            }
        }
        __syncthreads();
    }

    #pragma unroll
    for (int m = 0; m < 2; m++)
        #pragma unroll
        for (int j = 0; j < 2; j++) {
            int col = colbase + warp*16 + j*8 + 2*t;
            int r0  = m*16 + g;
            *(float2*)&outb[(size_t)r0*ostride + col] =
                make_float2(c[m][j][0], c[m][j][1]);
            *(float2*)&outb[(size_t)(r0+8)*ostride + col] =
                make_float2(c[m][j][2], c[m][j][3]);
        }
}

// ---------------- 2. QKV GEMM (tf32 mma, 64-wide N, K-split 8) ----------------
__global__ void __launch_bounds__(128) k_gemm_qkv(const float* __restrict__ Wq,
                                                  const float* __restrict__ Wk,
                                                  const float* __restrict__ Wv) {
    extern __shared__ float gsm[];
    int colbase = blockIdx.x * GNB;
    const float* Wsrc; int wstride, cb;
    if (colbase < 4096)       { Wsrc = Wq; wstride = 4096; cb = colbase; }
    else if (colbase < 5120)  { Wsrc = Wk; wstride = 1024; cb = colbase - 4096; }
    else                      { Wsrc = Wv; wstride = 1024; cb = colbase - 5120; }
    float* outb = g_part_qkv + (size_t)blockIdx.y * NTOK * QKV_COLS;
    gemm_body(g_hT, Wsrc, wstride, cb, blockIdx.y * GKRANGE,
              outb, QKV_COLS, colbase, gsm);
}

// ---------------- 3. reduce K-splits + RoPE ----------------
__global__ void k_reduce_rope(const float* __restrict__ cosb,
                              const float* __restrict__ sinb) {
    int slot = blockIdx.x;
    int row  = blockIdx.y;
    int d    = threadIdx.x;
    int col  = slot*128 + d;

    float s = 0.f;
    #pragma unroll
    for (int i = 0; i < GSPLIT; i++)
        s += g_part_qkv[((size_t)i*NTOK + row)*QKV_COLS + col];

    __shared__ float x[128];
    x[d] = s;
    __syncthreads();

    if (slot < 40) {
        float c  = cosb[row*128 + d];
        float sn = sinb[row*128 + d];
        float rot = (d < 64) ? -x[d + 64] : x[d - 64];
        float val = s*c + rot*sn;
        if (slot < 32) g_q[(size_t)row*4096 + col] = val;
        else           g_k[(size_t)row*1024 + (slot-32)*128 + d] = val;
    } else {
        g_v[(size_t)row*1024 + (slot-40)*128 + d] = s;
    }
}

// ---------------- 4. attention: R9 config (2-stage, 4 heads/block, 2KB TMA) ----------------
__device__ __forceinline__ void stage8(float* sm, unsigned mbK, unsigned mbV,
        int stg, int c0, int cl, int s1, int b, int kv0, int cap,
        const float* Kc, const float* Vc, int tid) {
    int nv = min(CH, s1 - c0);
    if (tid == 0) {
        mbar_expect_tx(mbK, (unsigned)nv * 2048u);
        mbar_expect_tx(mbV, (unsigned)nv * 2048u);
    }
    if (tid < 16) {
        int p = tid & 7;
        if (p < nv) {
            int sg = c0 + p;
            bool isV = tid >= 8;
            const float* src;
            if (sg < cl) {
                src = (isV ? Vc : Kc) + (((size_t)b*cap + sg)*NKV + kv0)*HD;
            } else {
                int row = b*QQ + (sg - cl);
                src = (isV ? g_v : g_k) + ((size_t)row*(NKV*HD) + kv0*HD);
            }
            float* dstp = sm + stg*STG_FLOATS + (isV ? OFF_VS + p*ROW_V : p*ROW_K);
            bulk_cp(smem_u32(dstp), src, 2048u, isV ? mbV : mbK);
        }
    }
}

__global__ void __launch_bounds__(128, 3) k_attn(const float* __restrict__ Kc,
                       const float* __restrict__ Vc,
                       const int* __restrict__ cache_lens, int cap) {
    extern __shared__ float sm[];
    unsigned mbb  = smem_u32(sm + OFF_MB_A);
    unsigned mbK0 = mbb,       mbK1 = mbb + 8;
    unsigned mbV0 = mbb + 16,  mbV1 = mbb + 24;

    int tid  = threadIdx.x;
    int warp = tid >> 5;
    int lane = tid & 31;
    int g    = lane >> 2;
    int t    = lane & 3;

    int split = blockIdx.x;
    int kv0   = blockIdx.y * 4;
    int b     = blockIdx.z;
    int kvh   = kv0 + warp;

    int cl = cache_lens[b];
    int n_total = cl + QQ;
    int len = (n_total + NSPLIT - 1) / NSPLIT;
    int s0 = split * len;
    int s1 = min(s0 + len, n_total);
    size_t pbase = (((size_t)(b*NKV + kvh))*NSPLIT + split)*16;

    if (s0 >= s1) {
        if (lane < 16) {
            g_pml[(pbase + lane)*2]     = 0.f;
            g_pml[(pbase + lane)*2 + 1] = 0.f;
        }
        for (int i = lane; i < 16*HD; i += 32)
            g_po[pbase*HD + i] = 0.f;
        return;
    }

    if (tid == 0) {
        mbar_init(mbK0, 1); mbar_init(mbK1, 1);
        mbar_init(mbV0, 1); mbar_init(mbV1, 1);
    }

    float aq[16][4];
    {
        int row0  = b*QQ + (g >> 2);
        int hq0   = kvh*GG + (g & 3);
        int row1  = b*QQ + ((g + 8) >> 2);
        int hq1   = kvh*GG + ((g + 8) & 3);
        const float* q0 = g_q + (size_t)row0*4096 + hq0*128;
        const float* q1 = g_q + (size_t)row1*4096 + hq1*128;
        #pragma unroll
        for (int ks = 0; ks < 16; ks++) {
            int kb = ks * 8;
            aq[ks][0] = tf32r(q0[kb + t]     * ATT_SCALE);
            aq[ks][1] = tf32r(q1[kb + t]     * ATT_SCALE);
            aq[ks][2] = tf32r(q0[kb + t + 4] * ATT_SCALE);
            aq[ks][3] = tf32r(q1[kb + t + 4] * ATT_SCALE);
        }
    }
    __syncthreads();

    float l0 = 0.f, l1 = 0.f;
    float oacc[16][4];
    #pragma unroll
    for (int nt = 0; nt < 16; nt++)
        #pragma unroll
        for (int j = 0; j < 4; j++) oacc[nt][j] = 0.f;

    int nch = (s1 - s0 + CH - 1) / CH;
    stage8(sm, mbK0, mbV0, 0, s0, cl, s1, b, kv0, cap, Kc, Vc, tid);

    for (int ci = 0; ci < nch; ci++) {
        int c0 = s0 + ci*CH;
        int bf = ci & 1;
        int par = (ci >> 1) & 1;

        if (ci + 1 < nch) {
            __syncthreads();
            stage8(sm, bf ? mbK0 : mbK1, bf ? mbV0 : mbV1, bf ^ 1,
                   c0 + CH, cl, s1, b, kv0, cap, Kc, Vc, tid);
        }

        mbar_wait(bf ? mbK1 : mbK0, par);

        float cA0 = 0.f, cA1 = 0.f, cA2 = 0.f, cA3 = 0.f;
        float cB0 = 0.f, cB1 = 0.f, cB2 = 0.f, cB3 = 0.f;
        {
            const float* Kb = sm + bf*STG_FLOATS + g*ROW_K + warp*128;
            #pragma unroll
            for (int ks = 0; ks < 16; ks += 2) {
                int kb = ks * 8;
                float b0 = Kb[kb + t];
                float b1 = Kb[kb + t + 4];
                mma_tf32(cA0, cA1, cA2, cA3,
                         aq[ks][0], aq[ks][1], aq[ks][2], aq[ks][3], b0, b1);
                float b2 = Kb[kb + 8 + t];
                float b3 = Kb[kb + 8 + t + 4];
                mma_tf32(cB0, cB1, cB2, cB3,
                         aq[ks+1][0], aq[ks+1][1], aq[ks+1][2], aq[ks+1][3], b2, b3);
            }
        }
        float c0r = cA0 + cB0, c1r = cA1 + cB1;
        float c2r = cA2 + cB2, c3r = cA3 + cB3;

        int Lg = min(s1, cl + (g >> 2) + 1) - c0;
        int Lh = min(s1, cl + ((g + 8) >> 2) + 1) - c0;
        int pc0 = 2*t, pc1 = 2*t + 1;

        float e00 = (pc0 < Lg) ? __expf(c0r) : 0.f;
        float e01 = (pc1 < Lg) ? __expf(c1r) : 0.f;
        float e10 = (pc0 < Lh) ? __expf(c2r) : 0.f;
        float e11 = (pc1 < Lh) ? __expf(c3r) : 0.f;

        l0 += e00 + e01;
        l1 += e10 + e11;

        e00 = tf32r(e00); e01 = tf32r(e01); e10 = tf32r(e10); e11 = tf32r(e11);

        int srcA = (g << 2) | (t >> 1);
        int srcB = srcA + 2;
        float f0a = __shfl_sync(0xffffffffu, e00, srcA);
        float f1a = __shfl_sync(0xffffffffu, e01, srcA);
        float f0b = __shfl_sync(0xffffffffu, e00, srcB);
        float f1b = __shfl_sync(0xffffffffu, e01, srcB);
        float h0a = __shfl_sync(0xffffffffu, e10, srcA);
        float h1a = __shfl_sync(0xffffffffu, e11, srcA);
        float h0b = __shfl_sync(0xffffffffu, e10, srcB);
        float h1b = __shfl_sync(0xffffffffu, e11, srcB);
        bool odd = (t & 1);
        float a0 = odd ? f1a : f0a;
        float a1 = odd ? h1a : h0a;
        float a2 = odd ? f1b : f0b;
        float a3 = odd ? h1b : h0b;

        mbar_wait(bf ? mbV1 : mbV0, par);

        {
            const float* Vb = sm + bf*STG_FLOATS + OFF_VS + warp*128;
            const float* Vr0 = Vb + t*ROW_V;
            const float* Vr1 = Vb + (t + 4)*ROW_V;
            #pragma unroll
            for (int nt = 0; nt < 16; nt++) {
                int n0 = nt*8 + g;
                float b0 = Vr0[n0];
                float b1 = Vr1[n0];
                mma_tf32(oacc[nt][0], oacc[nt][1], oacc[nt][2], oacc[nt][3],
                         a0, a1, a2, a3, b0, b1);
            }
        }
    }

    l0 += __shfl_xor_sync(0xffffffffu, l0, 1);
    l0 += __shfl_xor_sync(0xffffffffu, l0, 2);
    l1 += __shfl_xor_sync(0xffffffffu, l1, 1);
    l1 += __shfl_xor_sync(0xffffffffu, l1, 2);

    #pragma unroll
    for (int nt = 0; nt < 16; nt++) {
        int col = nt*8 + 2*t;
        *(float2*)(g_po + (pbase + g    )*HD + col) = make_float2(oacc[nt][0], oacc[nt][1]);
        *(float2*)(g_po + (pbase + g + 8)*HD + col) = make_float2(oacc[nt][2], oacc[nt][3]);
    }
    if (t == 0) {
        g_pml[(pbase + g)*2]          = 0.f;
        g_pml[(pbase + g)*2 + 1]      = l0;
        g_pml[(pbase + g + 8)*2]      = 0.f;
        g_pml[(pbase + g + 8)*2 + 1]  = l1;
    }
}

// ---------------- 5. combine: plain sums, wide grid ----------------
__global__ void k_combine() {
    int gid = blockIdx.x * 256 + threadIdx.x;
    int row = gid >> 5;
    int dgp = gid & 31;
    int d0  = dgp * 4;
    int bkv = row >> 4;
    int qi  = row & 15;
    int b   = bkv >> 3, kv = bkv & 7;
    size_t base = (size_t)bkv * NSPLIT * 16 + qi;

    float l_tot = 0.f;
    float4 o = make_float4(0.f, 0.f, 0.f, 0.f);
    #pragma unroll
    for (int s = 0; s < NSPLIT; s++) {
        size_t idx = base + (size_t)s * 16;
        l_tot += g_pml[idx*2 + 1];
        float4 x = *(const float4*)(g_po + idx*HD + d0);
        o.x += x.x; o.y += x.y; o.z += x.z; o.w += x.w;
    }
    float inv = 1.f / l_tot;
    int qo = qi >> 2, g = qi & 3;
    int tok  = b*QQ + qo;
    int head = kv*GG + g;
    size_t cbase = (size_t)(head*128 + d0)*NTOK + tok;
    g_attnT[cbase]          = tf32r(o.x * inv);
    g_attnT[cbase + NTOK]   = tf32r(o.y * inv);
    g_attnT[cbase + 2*NTOK] = tf32r(o.z * inv);
    g_attnT[cbase + 3*NTOK] = tf32r(o.w * inv);
}

// ---------------- 6. O GEMM (tf32 mma, 64-wide N, K-split 8) ----------------
__global__ void __launch_bounds__(128) k_gemm_o(const float* __restrict__ Wo) {
    extern __shared__ float gsm[];
    int colbase = blockIdx.x * GNB;
    float* outb = g_part_out + (size_t)blockIdx.y * NTOK * HH;
    gemm_body(g_attnT, Wo, 4096, colbase, blockIdx.y * GKRANGE,
              outb, HH, colbase, gsm);
}

// ---------------- 7. reduce O partials -> output ----------------
__global__ void k_reduce_out(float* __restrict__ out) {
    int idx = blockIdx.x * 256 + threadIdx.x;
    float s = 0.f;
    #pragma unroll
    for (int i = 0; i < GSPLIT; i++)
        s += g_part_out[(size_t)i * NTOK * HH + idx];
    out[idx] = s;
}

// ---------------- launch ----------------
extern "C" void kernel_launch(void* const* d_in, const int* in_sizes, int n_in,
                              void* d_out, int out_size) {
    const float* hidden = (const float*)d_in[0];
    const float* cosb   = (const float*)d_in[1];
    const float* sinb   = (const float*)d_in[2];
    const float* Wq     = (const float*)d_in[3];
    const float* Wk     = (const float*)d_in[4];
    const float* Wv     = (const float*)d_in[5];
    const float* Wo     = (const float*)d_in[6];
    const float* Kc     = (const float*)d_in[7];
    const float* Vc     = (const float*)d_in[8];
    const int*   cls    = (const int*)d_in[9];
    int cap = in_sizes[7] / (BB * NKV * HD);   // 4100

    static int attr_set = 0;
    if (!attr_set) {
        cudaFuncSetAttribute(k_attn, cudaFuncAttributeMaxDynamicSharedMemorySize,
                             SMEM_ATTN_BYTES);
        cudaFuncSetAttribute(k_gemm_qkv, cudaFuncAttributeMaxDynamicSharedMemorySize,
                             GSMEM_BYTES);
        cudaFuncSetAttribute(k_gemm_o, cudaFuncAttributeMaxDynamicSharedMemorySize,
                             GSMEM_BYTES);
        attr_set = 1;
    }

    k_transpose  <<<512, 256>>>(hidden);
    k_gemm_qkv   <<<dim3(96, GSPLIT), 128, GSMEM_BYTES>>>(Wq, Wk, Wv);
    k_reduce_rope<<<dim3(48, NTOK), 128>>>(cosb, sinb);
    k_attn       <<<dim3(NSPLIT, 2, BB), 128, SMEM_ATTN_BYTES>>>(Kc, Vc, cls, cap);
    k_combine    <<<128, 256>>>();
    k_gemm_o     <<<dim3(64, GSPLIT), 128, GSMEM_BYTES>>>(Wo);
    k_reduce_out <<<512, 256>>>((float*)d_out);
}